// round 7
// baseline (speedup 1.0000x reference)
#include <cuda_runtime.h>
#include <cuda_bf16.h>
#include <cstdint>

// Joiner: out[b,t,u,v] = sum_d relu(src[b,t,d] + tgt[b,u,d]) * W[v,d] + bias[v]
// GEMM view: M = B*T*U = 131072, N = V = 1024, K = D = 512.
// A[m,k] = relu(src[b,t,k] + tgt[b,u,k]),  m = ((b*T)+t)*U + u
// B[k,n] = W[n,k]

#define BB 8
#define TT 256
#define UU 64
#define DD 512
#define VV 1024
#define MM (BB*TT*UU)   // 131072

#define BM 128
#define BN 128
#define BK 16

__global__ __launch_bounds__(256)
void joiner_sgemm_kernel(const float* __restrict__ src,
                         const float* __restrict__ tgt,
                         const float* __restrict__ W,
                         const float* __restrict__ bias,
                         float* __restrict__ out)
{
    __shared__ float As[BK][BM];   // As[k][m]
    __shared__ float Bs[BK][BN];   // Bs[k][n]

    const int tid = threadIdx.x;
    const int tx  = tid & 15;      // 0..15 -> N micro
    const int ty  = tid >> 4;      // 0..15 -> M micro

    const int m0 = blockIdx.y * BM;
    const int n0 = blockIdx.x * BN;

    // A tile: 128 rows x 16 k = 512 float4 slots; each thread owns slots tid and tid+256.
    int a_src_base[2], a_tgt_base[2], a_r[2], a_kq[2];
    int b_w_base[2],  b_r[2],  b_kq[2];
#pragma unroll
    for (int i = 0; i < 2; i++) {
        int s  = tid + i * 256;
        int r  = s >> 2;          // row within tile (0..127)
        int kq = s & 3;           // which float4 along k (0..3)
        a_r[i]  = r;
        a_kq[i] = kq;
        int m = m0 + r;
        int u = m & (UU - 1);
        int t = (m >> 6) & (TT - 1);
        int b = m >> 14;          // m / (T*U)
        a_src_base[i] = ((b * TT) + t) * DD;
        a_tgt_base[i] = ((b * UU) + u) * DD;

        b_r[i]  = r;
        b_kq[i] = kq;
        b_w_base[i] = (n0 + r) * DD;
    }

    float acc[8][8];
#pragma unroll
    for (int i = 0; i < 8; i++)
#pragma unroll
        for (int j = 0; j < 8; j++) acc[i][j] = 0.0f;

    for (int k0 = 0; k0 < DD; k0 += BK) {
        // ---- Load A tile: relu(src + tgt) ----
#pragma unroll
        for (int i = 0; i < 2; i++) {
            const float4 sv = *(const float4*)(src + a_src_base[i] + k0 + a_kq[i] * 4);
            const float4 tv = *(const float4*)(tgt + a_tgt_base[i] + k0 + a_kq[i] * 4);
            float v0 = fmaxf(sv.x + tv.x, 0.0f);
            float v1 = fmaxf(sv.y + tv.y, 0.0f);
            float v2 = fmaxf(sv.z + tv.z, 0.0f);
            float v3 = fmaxf(sv.w + tv.w, 0.0f);
            int kk = a_kq[i] * 4;
            As[kk + 0][a_r[i]] = v0;
            As[kk + 1][a_r[i]] = v1;
            As[kk + 2][a_r[i]] = v2;
            As[kk + 3][a_r[i]] = v3;
        }
        // ---- Load B tile: W[n, k] ----
#pragma unroll
        for (int i = 0; i < 2; i++) {
            const float4 wv = *(const float4*)(W + b_w_base[i] + k0 + b_kq[i] * 4);
            int kk = b_kq[i] * 4;
            Bs[kk + 0][b_r[i]] = wv.x;
            Bs[kk + 1][b_r[i]] = wv.y;
            Bs[kk + 2][b_r[i]] = wv.z;
            Bs[kk + 3][b_r[i]] = wv.w;
        }
        __syncthreads();

        // ---- FMA mainloop ----
#pragma unroll
        for (int kk = 0; kk < BK; kk++) {
            float4 a0 = *(const float4*)&As[kk][ty * 4];
            float4 a1 = *(const float4*)&As[kk][64 + ty * 4];
            float4 b0 = *(const float4*)&Bs[kk][tx * 4];
            float4 b1 = *(const float4*)&Bs[kk][64 + tx * 4];
            float af[8] = {a0.x, a0.y, a0.z, a0.w, a1.x, a1.y, a1.z, a1.w};
            float bf[8] = {b0.x, b0.y, b0.z, b0.w, b1.x, b1.y, b1.z, b1.w};
#pragma unroll
            for (int i = 0; i < 8; i++)
#pragma unroll
                for (int j = 0; j < 8; j++)
                    acc[i][j] = fmaf(af[i], bf[j], acc[i][j]);
        }
        __syncthreads();
    }

    // ---- Epilogue: add bias, store ----
    const float4 bias0 = *(const float4*)(bias + n0 + tx * 4);
    const float4 bias1 = *(const float4*)(bias + n0 + 64 + tx * 4);
    const float bf0[4] = {bias0.x, bias0.y, bias0.z, bias0.w};
    const float bf1[4] = {bias1.x, bias1.y, bias1.z, bias1.w};

#pragma unroll
    for (int i = 0; i < 8; i++) {
        int row_local = (i < 4) ? (ty * 4 + i) : (64 + ty * 4 + (i - 4));
        long long m = (long long)(m0 + row_local);
        float* orow = out + m * VV + n0;
        float4 c0, c1;
        c0.x = acc[i][0] + bf0[0];
        c0.y = acc[i][1] + bf0[1];
        c0.z = acc[i][2] + bf0[2];
        c0.w = acc[i][3] + bf0[3];
        c1.x = acc[i][4] + bf1[0];
        c1.y = acc[i][5] + bf1[1];
        c1.z = acc[i][6] + bf1[2];
        c1.w = acc[i][7] + bf1[3];
        *(float4*)(orow + tx * 4)      = c0;
        *(float4*)(orow + 64 + tx * 4) = c1;
    }
}

// Write the two pass-through length arrays into the tail of d_out,
// immediately after the (B,T,U,V) tensor, CONVERTED TO FLOAT.
// The harness stores all outputs in the single __output__ dtype (float32),
// so int32 lengths must be value-converted, not bit-copied (the R4 bug).
__global__ void joiner_tail_kernel(const int* __restrict__ slen,
                                   const int* __restrict__ tlen,
                                   float* __restrict__ tail,
                                   int n_s, int n_t)
{
    int i = threadIdx.x;
    if (i < n_s)               tail[i] = (float)slen[i];
    else if (i < n_s + n_t)    tail[i] = (float)tlen[i - n_s];
}

extern "C" void kernel_launch(void* const* d_in, const int* in_sizes, int n_in,
                              void* d_out, int out_size)
{
    const float* src  = (const float*)d_in[0];
    const int*   slen = (const int*)  d_in[1];
    const float* tgt  = (const float*)d_in[2];
    const int*   tlen = (const int*)  d_in[3];
    const float* W    = (const float*)d_in[4];
    const float* bias = (const float*)d_in[5];
    float* out = (float*)d_out;

    dim3 grid(VV / BN, MM / BM);   // (8, 1024)
    joiner_sgemm_kernel<<<grid, 256>>>(src, tgt, W, bias, out);

    // Outputs are (main_tensor, source_lengths, target_lengths) concatenated
    // in the single output dtype (float32).
    const long long main_elems = (long long)MM * VV;  // 134217728
    int n_s = in_sizes[1];
    int n_t = in_sizes[3];
    float* tail = out + main_elems;
    joiner_tail_kernel<<<1, 32>>>(slen, tlen, tail, n_s, n_t);
}

// round 14
// speedup vs baseline: 1.9183x; 1.9183x over previous
#include <cuda_runtime.h>
#include <cuda_bf16.h>
#include <cstdint>

// Joiner: out[b,t,u,v] = sum_d relu(src[b,t,d] + tgt[b,u,d]) * W[v,d] + bias[v]
// GEMM: M = B*T*U = 131072, N = V = 1024, K = D = 512.
// mma.sync.m16n8k16 bf16 hi/lo split: A*B ~= Ah*Bh + Ah*Bl + Al*Bh (fp32 accum).
// (tcgen05 unavailable: harness builds PTX for compute_103 family target.)

#define BB 8
#define TT 256
#define UU 64
#define DD 512
#define VV 1024
#define MM (BB*TT*UU)   // 131072

#define AROW 80                  // 64B data + 16B pad -> conflict-free ldmatrix
#define TILEB (128*AROW)         // 10240
#define OFF_AH 0
#define OFF_AL (1*TILEB)
#define OFF_BH (2*TILEB)
#define OFF_BL (3*TILEB)
#define STAGE  (4*TILEB)         // 40960
#define SMEM_TOTAL (2*STAGE)     // 81920

// Pre-split bf16 hi/lo of W (1 MB each; L2-resident)
__device__ __nv_bfloat16 g_W_hi[VV * DD];
__device__ __nv_bfloat16 g_W_lo[VV * DD];

static __device__ __forceinline__ uint32_t smem_u32(const void* p) {
    uint32_t a;
    asm("{ .reg .u64 t; cvta.to.shared.u64 t, %1; cvt.u32.u64 %0, t; }"
        : "=r"(a) : "l"(p));
    return a;
}
static __device__ __forceinline__ void ldsm4(uint32_t* r, uint32_t addr) {
    asm volatile("ldmatrix.sync.aligned.m8n8.x4.shared.b16 {%0,%1,%2,%3}, [%4];"
                 : "=r"(r[0]), "=r"(r[1]), "=r"(r[2]), "=r"(r[3]) : "r"(addr));
}
static __device__ __forceinline__ void mma_bf16(float* d, const uint32_t* a,
                                                const uint32_t* b) {
    asm volatile("mma.sync.aligned.m16n8k16.row.col.f32.bf16.bf16.f32 "
                 "{%0,%1,%2,%3}, {%4,%5,%6,%7}, {%8,%9}, {%0,%1,%2,%3};"
                 : "+f"(d[0]), "+f"(d[1]), "+f"(d[2]), "+f"(d[3])
                 : "r"(a[0]), "r"(a[1]), "r"(a[2]), "r"(a[3]),
                   "r"(b[0]), "r"(b[1]));
}
static __device__ __forceinline__ void cp16(uint32_t s, const void* g) {
    asm volatile("cp.async.cg.shared.global [%0], [%1], 16;"
                 :: "r"(s), "l"(g) : "memory");
}
static __device__ __forceinline__ uint32_t pack_bf2(float lo, float hi) {
    __nv_bfloat162 p = __floats2bfloat162_rn(lo, hi);
    return *(uint32_t*)&p;
}

// ---------------- W hi/lo split precompute ----------------
__global__ void w_split_kernel(const float* __restrict__ W) {
    int i = (blockIdx.x * 256 + threadIdx.x) * 4;
    float4 w = *(const float4*)(W + i);
    float v[4] = {w.x, w.y, w.z, w.w};
#pragma unroll
    for (int j = 0; j < 4; j++) {
        __nv_bfloat16 h = __float2bfloat16_rn(v[j]);
        float r = v[j] - __bfloat162float(h);
        g_W_hi[i + j] = h;
        g_W_lo[i + j] = __float2bfloat16_rn(r);
    }
}

// ---------------- Main HMMA GEMM ----------------
__global__ __launch_bounds__(256)
void joiner_mma_kernel(const float* __restrict__ src,
                       const float* __restrict__ tgt,
                       const float* __restrict__ bias,
                       float* __restrict__ out)
{
    extern __shared__ char smem[];
    const uint32_t sb = smem_u32(smem);
    const int tid = threadIdx.x;
    const int l = tid & 31, w = tid >> 5;
    const int warpM = w & 3, warpN = w >> 2;
    const int n0 = blockIdx.x * 128;
    const int m0 = blockIdx.y * 128;

    // ---- A build slot: one (row, k-half16) per thread ----
    const int r_a = tid >> 1, kh = tid & 1;
    const float* srcp;
    const float* tgtp;
    {
        int m = m0 + r_a;
        int u = m & (UU - 1);
        int t = (m >> 6) & (TT - 1);
        int b = m >> 14;
        srcp = src + (b * TT + t) * DD + kh * 16;
        tgtp = tgt + (b * UU + u) * DD + kh * 16;
    }
    const uint32_t a_sts = sb + r_a * AROW + kh * 32;   // + OFF_AH(0); +OFF_AL for lo

    // ---- B cp.async slots: 2 rows16B per thread per matrix ----
    const int rb0 = tid >> 2, rb1 = (tid + 256) >> 2, cq = tid & 3;
    const __nv_bfloat16* wh0 = g_W_hi + (n0 + rb0) * DD + cq * 8;
    const __nv_bfloat16* wh1 = g_W_hi + (n0 + rb1) * DD + cq * 8;
    const __nv_bfloat16* wl0 = g_W_lo + (n0 + rb0) * DD + cq * 8;
    const __nv_bfloat16* wl1 = g_W_lo + (n0 + rb1) * DD + cq * 8;
    const uint32_t bs0 = rb0 * AROW + cq * 16;
    const uint32_t bs1 = rb1 * AROW + cq * 16;

    // ---- ldmatrix per-lane offsets ----
    const uint32_t a_lane = (((l >> 3) & 1) * 8 + (l & 7)) * AROW + ((l >> 4) & 1) * 16;
    const uint32_t b_lane = (((l >> 4) & 1) * 8 + (l & 7)) * AROW + ((l >> 3) & 1) * 16;

    float acc[2][8][4];
#pragma unroll
    for (int i = 0; i < 2; i++)
#pragma unroll
        for (int j = 0; j < 8; j++)
#pragma unroll
            for (int q = 0; q < 4; q++) acc[i][j][q] = 0.0f;

    float4 sA[4], tA[4];

    // ---- Prologue: chunk 0 into stage 0 ----
    {
        uint32_t st = sb;
        cp16(st + OFF_BH + bs0, wh0);
        cp16(st + OFF_BH + bs1, wh1);
        cp16(st + OFF_BL + bs0, wl0);
        cp16(st + OFF_BL + bs1, wl1);
        asm volatile("cp.async.commit_group;" ::: "memory");
#pragma unroll
        for (int q = 0; q < 4; q++) {
            sA[q] = __ldg((const float4*)(srcp) + q);
            tA[q] = __ldg((const float4*)(tgtp) + q);
        }
        // convert + STS
        uint32_t hw[8], lw[8];
#pragma unroll
        for (int q = 0; q < 4; q++) {
            float f[4] = {fmaxf(sA[q].x + tA[q].x, 0.f), fmaxf(sA[q].y + tA[q].y, 0.f),
                          fmaxf(sA[q].z + tA[q].z, 0.f), fmaxf(sA[q].w + tA[q].w, 0.f)};
            float h[4], lo[4];
#pragma unroll
            for (int e = 0; e < 4; e++) {
                h[e] = __bfloat162float(__float2bfloat16_rn(f[e]));
                lo[e] = f[e] - h[e];
            }
            hw[q * 2 + 0] = pack_bf2(h[0], h[1]);
            hw[q * 2 + 1] = pack_bf2(h[2], h[3]);
            lw[q * 2 + 0] = pack_bf2(lo[0], lo[1]);
            lw[q * 2 + 1] = pack_bf2(lo[2], lo[3]);
        }
        *(uint4*)(smem + (a_sts - sb) + OFF_AH)      = *(uint4*)&hw[0];
        *(uint4*)(smem + (a_sts - sb) + OFF_AH + 16) = *(uint4*)&hw[4];
        *(uint4*)(smem + (a_sts - sb) + OFF_AL)      = *(uint4*)&lw[0];
        *(uint4*)(smem + (a_sts - sb) + OFF_AL + 16) = *(uint4*)&lw[4];
        asm volatile("cp.async.wait_group 0;" ::: "memory");
    }
    __syncthreads();

    const uint32_t a_m_base0 = (warpM * 32) * AROW + a_lane;
    const uint32_t b_n_base0 = (warpN * 64) * AROW + b_lane;

    for (int c = 0; c < 16; c++) {
        const uint32_t cur = sb + (c & 1) * STAGE;
        const uint32_t nxt = sb + ((c + 1) & 1) * STAGE;

        if (c < 15) {
            const int ko = (c + 1) * 32;
            cp16(nxt + OFF_BH + bs0, wh0 + ko);
            cp16(nxt + OFF_BH + bs1, wh1 + ko);
            cp16(nxt + OFF_BL + bs0, wl0 + ko);
            cp16(nxt + OFF_BL + bs1, wl1 + ko);
            asm volatile("cp.async.commit_group;" ::: "memory");
#pragma unroll
            for (int q = 0; q < 4; q++) {
                sA[q] = __ldg((const float4*)(srcp + ko) + q);
                tA[q] = __ldg((const float4*)(tgtp + ko) + q);
            }
        }

        // ---- compute on current stage ----
#pragma unroll
        for (int ks = 0; ks < 2; ks++) {
            uint32_t ah[2][4], al_[2][4], bh[4][4], bl[4][4];
#pragma unroll
            for (int mt = 0; mt < 2; mt++) {
                uint32_t ao = cur + (a_m_base0 + mt * 16 * AROW) + ks * 32;
                ldsm4(ah[mt],  ao + OFF_AH);
                ldsm4(al_[mt], ao + OFF_AL);
            }
#pragma unroll
            for (int bt = 0; bt < 4; bt++) {
                uint32_t bo = cur + (b_n_base0 + bt * 16 * AROW) + ks * 32;
                ldsm4(bh[bt], bo + OFF_BH);
                ldsm4(bl[bt], bo + OFF_BL);
            }
#pragma unroll
            for (int mt = 0; mt < 2; mt++)
#pragma unroll
                for (int bt = 0; bt < 4; bt++)
#pragma unroll
                    for (int h = 0; h < 2; h++) {
                        const int nt = bt * 2 + h;
                        mma_bf16(acc[mt][nt], ah[mt],  &bh[bt][h * 2]);
                        mma_bf16(acc[mt][nt], ah[mt],  &bl[bt][h * 2]);
                        mma_bf16(acc[mt][nt], al_[mt], &bh[bt][h * 2]);
                    }
        }

        if (c < 15) {
            // convert + STS next A chunk
            uint32_t hw[8], lw[8];
#pragma unroll
            for (int q = 0; q < 4; q++) {
                float f[4] = {fmaxf(sA[q].x + tA[q].x, 0.f), fmaxf(sA[q].y + tA[q].y, 0.f),
                              fmaxf(sA[q].z + tA[q].z, 0.f), fmaxf(sA[q].w + tA[q].w, 0.f)};
                float h[4], lo[4];
#pragma unroll
                for (int e = 0; e < 4; e++) {
                    h[e] = __bfloat162float(__float2bfloat16_rn(f[e]));
                    lo[e] = f[e] - h[e];
                }
                hw[q * 2 + 0] = pack_bf2(h[0], h[1]);
                hw[q * 2 + 1] = pack_bf2(h[2], h[3]);
                lw[q * 2 + 0] = pack_bf2(lo[0], lo[1]);
                lw[q * 2 + 1] = pack_bf2(lo[2], lo[3]);
            }
            char* nb = smem + ((c + 1) & 1) * STAGE + (a_sts - sb);
            *(uint4*)(nb + OFF_AH)      = *(uint4*)&hw[0];
            *(uint4*)(nb + OFF_AH + 16) = *(uint4*)&hw[4];
            *(uint4*)(nb + OFF_AL)      = *(uint4*)&lw[0];
            *(uint4*)(nb + OFF_AL + 16) = *(uint4*)&lw[4];
            asm volatile("cp.async.wait_group 0;" ::: "memory");
        }
        __syncthreads();
    }

    // ---- Epilogue: bias + store (fp32) ----
    const int g = l >> 2, tig = l & 3;
#pragma unroll
    for (int nt = 0; nt < 8; nt++) {
        const int col = n0 + warpN * 64 + nt * 8 + 2 * tig;
        const float2 bz = __ldg((const float2*)(bias + col));
#pragma unroll
        for (int mt = 0; mt < 2; mt++) {
            const int row0 = m0 + warpM * 32 + mt * 16 + g;
            float2 o0, o1;
            o0.x = acc[mt][nt][0] + bz.x;
            o0.y = acc[mt][nt][1] + bz.y;
            o1.x = acc[mt][nt][2] + bz.x;
            o1.y = acc[mt][nt][3] + bz.y;
            *(float2*)(out + (long long)row0 * VV + col)       = o0;
            *(float2*)(out + (long long)(row0 + 8) * VV + col) = o1;
        }
    }
}

// Tail: lengths converted to float (verified fix)
__global__ void joiner_tail_kernel(const int* __restrict__ slen,
                                   const int* __restrict__ tlen,
                                   float* __restrict__ tail,
                                   int n_s, int n_t)
{
    int i = threadIdx.x;
    if (i < n_s)            tail[i] = (float)slen[i];
    else if (i < n_s + n_t) tail[i] = (float)tlen[i - n_s];
}

extern "C" void kernel_launch(void* const* d_in, const int* in_sizes, int n_in,
                              void* d_out, int out_size)
{
    const float* src  = (const float*)d_in[0];
    const int*   slen = (const int*)  d_in[1];
    const float* tgt  = (const float*)d_in[2];
    const int*   tlen = (const int*)  d_in[3];
    const float* W    = (const float*)d_in[4];
    const float* bias = (const float*)d_in[5];
    float* out = (float*)d_out;

    cudaFuncSetAttribute(joiner_mma_kernel,
                         cudaFuncAttributeMaxDynamicSharedMemorySize, SMEM_TOTAL);

    w_split_kernel<<<(VV * DD) / (256 * 4), 256>>>(W);

    dim3 grid(VV / 128, MM / 128);   // (8, 1024)
    joiner_mma_kernel<<<grid, 256, SMEM_TOTAL>>>(src, tgt, bias, out);

    const long long main_elems = (long long)MM * VV;
    joiner_tail_kernel<<<1, 32>>>(slen, tlen, out + main_elems,
                                  in_sizes[1], in_sizes[3]);
}